// round 1
// baseline (speedup 1.0000x reference)
#include <cuda_runtime.h>
#include <cfloat>

// Problem: N=8192 tokens, K=4096, D=1024.
//   idx[n] = argmax_k x[n,k]  (first-occurrence tie-break)
//   out[n,d] = W[d, idx[n]]   (column gather from W [D,K] row-major)
//
// Strategy: transpose W -> Wt [K,D] in device scratch (16 MB, fits L2),
// then one block per token: argmax of its x row + coalesced copy of Wt row.

#define NTOK 8192
#define KDIM 4096
#define DDIM 1024

// 16 MB scratch for W^T (allocation-free rule: __device__ global)
__device__ float g_Wt[(size_t)KDIM * DDIM];

// ---------------- transpose W [D,K] -> Wt [K,D] ----------------
#define TILE 32
__global__ void transpose_kernel(const float* __restrict__ W) {
    __shared__ float tile[TILE][TILE + 1];
    int k0 = blockIdx.x * TILE;
    int d0 = blockIdx.y * TILE;
    int tx = threadIdx.x;   // 0..31
    int ty = threadIdx.y;   // 0..7

    // load 32x32 tile of W (rows = d, cols = k), coalesced along k
    #pragma unroll
    for (int i = ty; i < TILE; i += 8)
        tile[i][tx] = W[(size_t)(d0 + i) * KDIM + (k0 + tx)];
    __syncthreads();

    // write transposed, coalesced along d
    #pragma unroll
    for (int i = ty; i < TILE; i += 8)
        g_Wt[(size_t)(k0 + i) * DDIM + (d0 + tx)] = tile[tx][i];
}

// ---------------- fused argmax + row gather ----------------
// One block (256 threads) per token.
__global__ void __launch_bounds__(256) argmax_gather_kernel(
    const float* __restrict__ x, float* __restrict__ out)
{
    const int n   = blockIdx.x;
    const int tid = threadIdx.x;

    // --- per-thread argmax over float4 chunks (indices visited in increasing order) ---
    const float4* xr = reinterpret_cast<const float4*>(x + (size_t)n * KDIM);
    float best = -FLT_MAX;
    int   bi   = 0x7fffffff;

    #pragma unroll
    for (int it = 0; it < (KDIM / 4) / 256; ++it) {
        int c = tid + it * 256;
        float4 v = xr[c];
        int base = c * 4;
        if (v.x > best) { best = v.x; bi = base + 0; }
        if (v.y > best) { best = v.y; bi = base + 1; }
        if (v.z > best) { best = v.z; bi = base + 2; }
        if (v.w > best) { best = v.w; bi = base + 3; }
    }

    // --- warp reduce (smaller index wins ties) ---
    #pragma unroll
    for (int off = 16; off > 0; off >>= 1) {
        float ov = __shfl_down_sync(0xffffffffu, best, off);
        int   oi = __shfl_down_sync(0xffffffffu, bi,   off);
        if (ov > best || (ov == best && oi < bi)) { best = ov; bi = oi; }
    }

    // --- block reduce across 8 warps ---
    __shared__ float s_val[8];
    __shared__ int   s_idx[8];
    __shared__ int   s_final;
    int warp = tid >> 5;
    int lane = tid & 31;
    if (lane == 0) { s_val[warp] = best; s_idx[warp] = bi; }
    __syncthreads();
    if (warp == 0) {
        best = (lane < 8) ? s_val[lane] : -FLT_MAX;
        bi   = (lane < 8) ? s_idx[lane] : 0x7fffffff;
        #pragma unroll
        for (int off = 4; off > 0; off >>= 1) {
            float ov = __shfl_down_sync(0xffffffffu, best, off);
            int   oi = __shfl_down_sync(0xffffffffu, bi,   off);
            if (ov > best || (ov == best && oi < bi)) { best = ov; bi = oi; }
        }
        if (lane == 0) s_final = bi;
    }
    __syncthreads();
    const int idx = s_final;

    // --- coalesced row copy: out[n, :] = Wt[idx, :]  (1024 floats = 256 float4) ---
    const float4* src = reinterpret_cast<const float4*>(g_Wt + (size_t)idx * DDIM);
    float4*       dst = reinterpret_cast<float4*>(out + (size_t)n * DDIM);
    dst[tid] = src[tid];
}

extern "C" void kernel_launch(void* const* d_in, const int* in_sizes, int n_in,
                              void* d_out, int out_size) {
    const float* x = (const float*)d_in[0];   // [N, K]
    const float* W = (const float*)d_in[1];   // [D, K]
    float* out = (float*)d_out;               // [N, D]

    // transpose W first (independent of x); stream-serialized before gather
    transpose_kernel<<<dim3(KDIM / TILE, DDIM / TILE), dim3(32, 8)>>>(W);
    argmax_gather_kernel<<<NTOK, 256>>>(x, out);
}

// round 2
// speedup vs baseline: 1.0062x; 1.0062x over previous
#include <cuda_runtime.h>
#include <cfloat>

// N=8192 tokens, K=4096, D=1024.
//   idx[n] = argmax_k x[n,k]  (first-occurrence tie-break)
//   out[n,d] = W[d, idx[n]]   (column gather from W [D,K] row-major)
//
// K1: fused grid — 8192 blocks do per-token argmax -> g_idx, 1024 blocks
//     transpose W -> g_Wt [K,D] (independent work, overlapped in one launch).
// K2: coalesced row gather out[n,:] = g_Wt[idx[n],:] (Wt is L2-resident).

#define NTOK 8192
#define KDIM 4096
#define DDIM 1024

// scratch (allocation-free rule: __device__ globals)
__device__ float g_Wt[(size_t)KDIM * DDIM];   // 16 MB
__device__ int   g_idx[NTOK];

#define TP_TILE   64
#define TP_BLOCKS ((KDIM / TP_TILE) * (DDIM / TP_TILE))   // 64 * 16 = 1024

// ---------------- K1: fused argmax + transpose ----------------
__global__ void __launch_bounds__(256) fused_argmax_transpose_kernel(
    const float* __restrict__ x, const float* __restrict__ W)
{
    const int bid = blockIdx.x;
    const int tid = threadIdx.x;

    if (bid < NTOK) {
        // ---- per-token argmax over x[bid, :] ----
        const int n = bid;
        const float4* xr = reinterpret_cast<const float4*>(x + (size_t)n * KDIM);
        float best = -FLT_MAX;
        int   bi   = 0x7fffffff;

        #pragma unroll
        for (int it = 0; it < (KDIM / 4) / 256; ++it) {
            int c = tid + it * 256;
            float4 v = xr[c];
            int base = c * 4;
            if (v.x > best) { best = v.x; bi = base + 0; }
            if (v.y > best) { best = v.y; bi = base + 1; }
            if (v.z > best) { best = v.z; bi = base + 2; }
            if (v.w > best) { best = v.w; bi = base + 3; }
        }

        // warp reduce (smaller index wins ties)
        #pragma unroll
        for (int off = 16; off > 0; off >>= 1) {
            float ov = __shfl_down_sync(0xffffffffu, best, off);
            int   oi = __shfl_down_sync(0xffffffffu, bi,   off);
            if (ov > best || (ov == best && oi < bi)) { best = ov; bi = oi; }
        }

        // block reduce across 8 warps
        __shared__ float s_val[8];
        __shared__ int   s_idx[8];
        int warp = tid >> 5;
        int lane = tid & 31;
        if (lane == 0) { s_val[warp] = best; s_idx[warp] = bi; }
        __syncthreads();
        if (warp == 0) {
            best = (lane < 8) ? s_val[lane] : -FLT_MAX;
            bi   = (lane < 8) ? s_idx[lane] : 0x7fffffff;
            #pragma unroll
            for (int off = 4; off > 0; off >>= 1) {
                float ov = __shfl_down_sync(0xffffffffu, best, off);
                int   oi = __shfl_down_sync(0xffffffffu, bi,   off);
                if (ov > best || (ov == best && oi < bi)) { best = ov; bi = oi; }
            }
            if (lane == 0) g_idx[n] = bi;
        }
    } else {
        // ---- transpose one 64x64 tile of W [D,K] -> g_Wt [K,D] ----
        __shared__ float t[TP_TILE][TP_TILE + 1];
        const int tile = bid - NTOK;                 // 0 .. 1023
        const int k0 = (tile % (KDIM / TP_TILE)) * TP_TILE;
        const int d0 = (tile / (KDIM / TP_TILE)) * TP_TILE;
        const int tx = tid & 15;     // float4 lane along fast dim
        const int ty = tid >> 4;     // row 0..15

        // load: 16 rows/iter, each row 16 float4 = 64 floats along k (coalesced)
        #pragma unroll
        for (int i = 0; i < 4; ++i) {
            int r = ty + 16 * i;     // d offset within tile
            float4 v = *reinterpret_cast<const float4*>(
                W + (size_t)(d0 + r) * KDIM + (k0 + 4 * tx));
            t[r][4 * tx + 0] = v.x;
            t[r][4 * tx + 1] = v.y;
            t[r][4 * tx + 2] = v.z;
            t[r][4 * tx + 3] = v.w;
        }
        __syncthreads();

        // write: rows along k, 64 floats along d per row (coalesced float4)
        #pragma unroll
        for (int i = 0; i < 4; ++i) {
            int r = ty + 16 * i;     // k offset within tile
            float4 v;
            v.x = t[4 * tx + 0][r];
            v.y = t[4 * tx + 1][r];
            v.z = t[4 * tx + 2][r];
            v.w = t[4 * tx + 3][r];
            *reinterpret_cast<float4*>(
                g_Wt + (size_t)(k0 + r) * DDIM + (d0 + 4 * tx)) = v;
        }
    }
}

// ---------------- K2: row gather ----------------
__global__ void __launch_bounds__(256) gather_kernel(float* __restrict__ out)
{
    const int n   = blockIdx.x;
    const int tid = threadIdx.x;
    const int idx = g_idx[n];    // uniform load, broadcast

    const float4* src = reinterpret_cast<const float4*>(g_Wt + (size_t)idx * DDIM);
    float4*       dst = reinterpret_cast<float4*>(out + (size_t)n * DDIM);
    dst[tid] = src[tid];         // 256 * 16B = 4 KB row copy
}

extern "C" void kernel_launch(void* const* d_in, const int* in_sizes, int n_in,
                              void* d_out, int out_size) {
    const float* x = (const float*)d_in[0];   // [N, K]
    const float* W = (const float*)d_in[1];   // [D, K]
    float* out = (float*)d_out;               // [N, D]

    fused_argmax_transpose_kernel<<<NTOK + TP_BLOCKS, 256>>>(x, W);
    gather_kernel<<<NTOK, 256>>>(out);
}